// round 5
// baseline (speedup 1.0000x reference)
#include <cuda_runtime.h>
#include <cstdint>

#define OBS_DIM   256
#define HID_DIM   512
#define ACT_DIM   18
#define BATCH     1024
#define ETA       0.01f
#define LAMBDA    0.95f
#define BPB       8      // batches per block

__global__ void q_init_kernel(const float* __restrict__ bq, float* __restrict__ q) {
    int i = blockIdx.x * blockDim.x + threadIdx.x;
    if (i < BATCH * ACT_DIM) q[i] = bq[i % ACT_DIM];
}

__device__ __forceinline__ void cp16(unsigned int dst_smem, const void* src) {
    asm volatile("cp.async.cg.shared.global [%0], [%1], 16;"
                 :: "r"(dst_smem), "l"(src));
}
__device__ __forceinline__ float tanh_approx(float x) {
    float r;
    asm("tanh.approx.f32 %0, %1;" : "=f"(r) : "f"(x));
    return r;
}

// Fused MPN step + Hebbian update + q-head.
// Block: 8 warps; hidden rows [bx*8,+8) x 8 batches. M rows are staged
// gmem->smem via per-warp cp.async double buffering (no destination regs,
// each lane stages exactly the 16B chunks it later consumes, so per-warp
// cp.async.wait_group suffices - no block barrier in the mainloop).
__global__ __launch_bounds__(256, 7) void mpn_step_kernel(
    const float* __restrict__ obs,
    const float* __restrict__ M,
    const float* __restrict__ W,
    const float* __restrict__ bh,
    const float* __restrict__ Wq,
    float* __restrict__ newM,
    float* __restrict__ q)
{
    __shared__ float4 xs[BPB * OBS_DIM / 4];    // 8 obs rows: 8 KB
    __shared__ float4 mbuf[2][8][OBS_DIM / 4];  // double-buffered M rows: 16 KB
    __shared__ float  hsh[BPB][8];

    const int b0    = blockIdx.y * BPB;
    const int hbase = blockIdx.x * 8;
    const int tid   = threadIdx.x;

    {
        const float4* og = reinterpret_cast<const float4*>(obs + (size_t)b0 * OBS_DIM);
        xs[tid]       = og[tid];
        xs[tid + 256] = og[tid + 256];
    }
    __syncthreads();

    const int warp = tid >> 5;
    const int lane = tid & 31;
    const int h    = hbase + warp;

    const float bias = __ldg(bh + h);
    const float4* wp = reinterpret_cast<const float4*>(W + (size_t)h * OBS_DIM);
    const float4 w0  = __ldg(wp + lane);
    const float4 w1  = __ldg(wp + lane + 32);

    const size_t bstride = (size_t)HID_DIM * OBS_DIM / 4;  // float4 units
    const float4* Mrow = reinterpret_cast<const float4*>(M)
                       + ((size_t)b0 * HID_DIM + h) * (OBS_DIM / 4);
    float4* Orow = reinterpret_cast<float4*>(newM)
                 + ((size_t)b0 * HID_DIM + h) * (OBS_DIM / 4);

    const unsigned int sm_a = (unsigned int)__cvta_generic_to_shared(&mbuf[0][warp][lane]);
    const unsigned int sm_b = (unsigned int)__cvta_generic_to_shared(&mbuf[1][warp][lane]);

    // Prologue: stage batch 0 into buffer 0.
    cp16(sm_a,       Mrow + lane);
    cp16(sm_a + 512, Mrow + lane + 32);
    asm volatile("cp.async.commit_group;");

    #pragma unroll
    for (int i = 0; i < BPB; i++) {
        // Stage batch i+1 into the other buffer; commit (possibly empty) group.
        if (i + 1 < BPB) {
            const float4* Mn = Mrow + (size_t)(i + 1) * bstride;
            const unsigned int d = ((i + 1) & 1) ? sm_b : sm_a;
            cp16(d,       Mn + lane);
            cp16(d + 512, Mn + lane + 32);
        }
        asm volatile("cp.async.commit_group;");
        // All groups except the newest complete => batch i's data is in smem.
        asm volatile("cp.async.wait_group 1;");

        const float4 m0 = mbuf[i & 1][warp][lane];
        const float4 m1 = mbuf[i & 1][warp][lane + 32];
        const float4 x0 = xs[i * 64 + lane];
        const float4 x1 = xs[i * 64 + lane + 32];

        // sum_o W[h,o] * obs[b,o] * (1 + M[b,h,o])
        float acc =
            w0.x * x0.x * (1.0f + m0.x) + w0.y * x0.y * (1.0f + m0.y) +
            w0.z * x0.z * (1.0f + m0.z) + w0.w * x0.w * (1.0f + m0.w) +
            w1.x * x1.x * (1.0f + m1.x) + w1.y * x1.y * (1.0f + m1.y) +
            w1.z * x1.z * (1.0f + m1.z) + w1.w * x1.w * (1.0f + m1.w);

        #pragma unroll
        for (int o = 16; o; o >>= 1)
            acc += __shfl_xor_sync(0xffffffffu, acc, o);

        const float hv = tanh_approx(acc + bias);
        const float eh = ETA * hv;

        float4 n0, n1;
        n0.x = LAMBDA * m0.x + eh * x0.x;  n0.y = LAMBDA * m0.y + eh * x0.y;
        n0.z = LAMBDA * m0.z + eh * x0.z;  n0.w = LAMBDA * m0.w + eh * x0.w;
        n1.x = LAMBDA * m1.x + eh * x1.x;  n1.y = LAMBDA * m1.y + eh * x1.y;
        n1.z = LAMBDA * m1.z + eh * x1.z;  n1.w = LAMBDA * m1.w + eh * x1.w;

        float4* Ob = Orow + (size_t)i * bstride;
        __stcs(Ob + lane,      n0);
        __stcs(Ob + lane + 32, n1);

        if (lane == 0) hsh[i][warp] = hv;
    }

    __syncthreads();

    // q-head epilogue: warp 0 reduces the block's 8 h-rows, 18 REDs per batch.
    if (warp == 0 && lane < ACT_DIM) {
        const float4* wq = reinterpret_cast<const float4*>(
            Wq + (size_t)lane * HID_DIM + hbase);
        const float4 a0 = __ldg(wq);
        const float4 a1 = __ldg(wq + 1);
        #pragma unroll
        for (int i = 0; i < BPB; i++) {
            float qv = a0.x * hsh[i][0] + a0.y * hsh[i][1]
                     + a0.z * hsh[i][2] + a0.w * hsh[i][3]
                     + a1.x * hsh[i][4] + a1.y * hsh[i][5]
                     + a1.z * hsh[i][6] + a1.w * hsh[i][7];
            atomicAdd(q + (size_t)(b0 + i) * ACT_DIM + lane, qv);
        }
    }
}

extern "C" void kernel_launch(void* const* d_in, const int* in_sizes, int n_in,
                              void* d_out, int out_size) {
    const float* obs = (const float*)d_in[0];  // [1024, 256]
    const float* M   = (const float*)d_in[1];  // [1024, 512, 256]
    const float* W   = (const float*)d_in[2];  // [512, 256]
    const float* bh  = (const float*)d_in[3];  // [512]
    const float* Wq  = (const float*)d_in[4];  // [18, 512]
    const float* bq  = (const float*)d_in[5];  // [18]

    float* q    = (float*)d_out;               // [1024, 18]
    float* newM = q + (size_t)BATCH * ACT_DIM; // [1024, 512, 256]

    q_init_kernel<<<(BATCH * ACT_DIM + 255) / 256, 256>>>(bq, q);

    dim3 grid(HID_DIM / 8, BATCH / BPB);
    mpn_step_kernel<<<grid, 256>>>(obs, M, W, bh, Wq, newM, q);
}